// round 9
// baseline (speedup 1.0000x reference)
#include <cuda_runtime.h>
#include <cstdint>

#define NROWS   256
#define TM1     131072                     // outputs per row
#define TROW    131073                     // edc row length
#define CTAS_PER_ROW 128                   // 1024 outputs per CTA
#define GRID    (NROWS * CTAS_PER_ROW)     // 32768 CTAs

// Decoupled-lookback status: one word per CTA.
//   0        = invalid
//   2 | p    = aggregate ready, parity p
//   4 | p    = inclusive prefix ready, parity p
// Payload and flag share one 32-bit word -> plain volatile ld/st suffice.
__device__ volatile unsigned int g_status[GRID];

__device__ __forceinline__ float sqrt_approx(float x) {
    float r;
    asm("sqrt.approx.f32 %0, %1;" : "=f"(r) : "f"(x));
    return r;
}

// ---------------------------------------------------------------------------
// K0: zero the status array (131 KB). 64 CTAs x 512 threads.
// ---------------------------------------------------------------------------
__global__ void __launch_bounds__(512)
init_status_kernel()
{
    g_status[blockIdx.x * 512 + threadIdx.x] = 0u;
}

// ---------------------------------------------------------------------------
// K1 (fused): single pass over flips+edc with per-row decoupled lookback.
// CTA b: row = b>>7, c = b&127, outputs [b*1024, b*1024+1024).
// ---------------------------------------------------------------------------
__global__ void __launch_bounds__(256)
fused_kernel(const float* __restrict__ edc,
             const int*   __restrict__ flips,
             float*       __restrict__ out)
{
    const int blk  = blockIdx.x;
    const int tid  = threadIdx.x;
    const int lane = tid & 31;
    const int warp = tid >> 5;                       // 8 warps
    const uint32_t ltmask = (1u << lane) - 1u;

    const int row = blk >> 7;
    const int c   = blk & (CTAS_PER_ROW - 1);
    const int gidx = blk * 256 + tid;                // 4-output group id

    // ---- flips: one int4 per thread (this thread's 4 flip bits) ----------
    const int4 f = __ldg(reinterpret_cast<const int4*>(flips) + gidx);
    uint32_t p0 = (uint32_t)f.x & 1u;
    const uint32_t p1 = (uint32_t)f.y & 1u;
    const uint32_t p2 = (uint32_t)f.z & 1u;
    const uint32_t p3 = (uint32_t)f.w & 1u;
    if (c == 0 && tid == 0) p0 = 0u;                 // flips[:,0] never applied

    const uint32_t tp  = p0 ^ p1 ^ p2 ^ p3;
    const uint32_t bal = __ballot_sync(0xffffffffu, tp != 0u);
    const uint32_t laneExcl = (uint32_t)__popc(bal & ltmask) & 1u;
    const uint32_t wtot     = (uint32_t)__popc(bal) & 1u;

    __shared__ uint32_t sW[8];
    __shared__ uint32_t sPrefix;
    if (lane == 0) sW[warp] = wtot;
    __syncthreads();

    uint32_t ctaTot = 0u, warpExcl = 0u;
#pragma unroll
    for (int w = 0; w < 8; ++w) {
        const uint32_t v = sW[w];
        ctaTot ^= v;
        if (w < warp) warpExcl ^= v;
    }

    // ---- decoupled lookback (lane 0 of warp 0) ---------------------------
    if (warp == 0 && lane == 0) {
        if (c == 0) {
            g_status[blk] = 4u | ctaTot;             // inclusive prefix = own agg
            sPrefix = 0u;
        } else {
            g_status[blk] = 2u | ctaTot;             // publish aggregate first
            uint32_t excl = 0u;
            int pb = blk - 1;
            for (;;) {
                const uint32_t s = g_status[pb];
                if (s == 0u) continue;               // not yet published: spin
                excl ^= s & 1u;
                if (s & 4u) break;                   // inclusive prefix: done
                --pb;                                // aggregate: keep walking
            }
            g_status[blk] = 4u | ((excl ^ ctaTot) & 1u);
            sPrefix = excl;
        }
    }
    __syncthreads();
    const uint32_t pref = sPrefix;

    // ---- amp body (identical math to R8 amp_kernel) ----------------------
    // edc flat offset of first output = 4*gidx + row (TROW = TM1 + 1)
    const unsigned u0    = ((unsigned)gidx << 2) + (unsigned)row;
    const unsigned ub    = u0 & ~3u;                 // 16B-aligned down
    const int      delta = row & 3;                  // uniform per CTA

    const float4* ep = reinterpret_cast<const float4*>(edc) + (ub >> 2);
    const float4 A = __ldg(ep);
    const float4 B = __ldg(ep + 1);

    float e0, e1, e2, e3, e4;
    switch (delta) {
    case 0:  e0 = A.x; e1 = A.y; e2 = A.z; e3 = A.w; e4 = B.x; break;
    case 1:  e0 = A.y; e1 = A.z; e2 = A.w; e3 = B.x; e4 = B.y; break;
    case 2:  e0 = A.z; e1 = A.w; e2 = B.x; e3 = B.y; e4 = B.z; break;
    default: e0 = A.w; e1 = B.x; e2 = B.y; e3 = B.z; e4 = B.w; break;
    }

    uint32_t run = pref ^ warpExcl ^ laneExcl;
    float4 o;
    run ^= p0;
    o.x = __uint_as_float(__float_as_uint(sqrt_approx(fmaxf(e0 - e1, 0.0f))) ^ (run << 31));
    run ^= p1;
    o.y = __uint_as_float(__float_as_uint(sqrt_approx(fmaxf(e1 - e2, 0.0f))) ^ (run << 31));
    run ^= p2;
    o.z = __uint_as_float(__float_as_uint(sqrt_approx(fmaxf(e2 - e3, 0.0f))) ^ (run << 31));
    run ^= p3;
    o.w = __uint_as_float(__float_as_uint(sqrt_approx(fmaxf(e3 - e4, 0.0f))) ^ (run << 31));

    reinterpret_cast<float4*>(out)[gidx] = o;
}

// ---------------------------------------------------------------------------
// Generic fallback: any (B, T). One CTA per row, chunked block-wide parity
// scan with a carried prefix. Only used if sizes don't match the constants.
// ---------------------------------------------------------------------------
__global__ void sticky_sign_generic(const float* __restrict__ edc,
                                    const int*   __restrict__ flips,
                                    float*       __restrict__ out,
                                    int T)
{
    const int row  = blockIdx.x;
    const int n    = T - 1;
    const int tid  = threadIdx.x;
    const int lane = tid & 31;
    const int warp = tid >> 5;

    const float* erow = edc   + (size_t)row * T;
    const int*   frow = flips + (size_t)row * n;
    float*       orow = out   + (size_t)row * n;

    __shared__ uint32_t sW[32];
    __shared__ uint32_t sCarry;
    if (tid == 0) sCarry = 0u;
    const int nwarps = (blockDim.x + 31) >> 5;
    if (tid < 32) sW[tid] = 0u;
    __syncthreads();

    for (int base = 0; base < n; base += blockDim.x) {
        const int i = base + tid;
        uint32_t f = 0u;
        if (i < n && i > 0) f = (uint32_t)frow[i] & 1u;

        const uint32_t m = __ballot_sync(0xffffffffu, f);
        const uint32_t laneIncl = (uint32_t)__popc(m & ((2u << lane) - 1u)) & 1u;
        if (lane == 0) sW[warp] = (uint32_t)__popc(m) & 1u;
        __syncthreads();

        uint32_t wpre = 0u, tot = 0u;
        for (int w = 0; w < nwarps; ++w) {
            uint32_t v = sW[w];
            tot ^= v;
            if (w < warp) wpre ^= v;
        }
        const uint32_t carry = sCarry;
        const uint32_t incl  = carry ^ wpre ^ laneIncl;

        if (i < n) {
            float amp = sqrtf(fmaxf(erow[i] - erow[i + 1], 0.0f));
            orow[i] = __uint_as_float(__float_as_uint(amp) ^ (incl << 31));
        }
        __syncthreads();
        if (tid == 0) sCarry = carry ^ tot;
        __syncthreads();
    }
}

extern "C" void kernel_launch(void* const* d_in, const int* in_sizes, int n_in,
                              void* d_out, int out_size)
{
    // Identify inputs by element count (edc has B extra elements).
    long long n0 = in_sizes[0];
    long long n1 = (n_in > 1) ? in_sizes[1] : 0;

    const float* edc;
    const int*   flips;
    long long ne, nf;
    if (n0 >= n1) {
        edc = (const float*)d_in[0];  flips = (const int*)d_in[1];
        ne = n0; nf = n1;
    } else {
        edc = (const float*)d_in[1];  flips = (const int*)d_in[0];
        ne = n1; nf = n0;
    }
    float* out = (float*)d_out;

    if (ne == (long long)NROWS * TROW && nf == (long long)NROWS * TM1) {
        init_status_kernel<<<GRID / 512, 512>>>();
        fused_kernel<<<GRID, 256>>>(edc, flips, out);
    } else {
        long long B = ne - nf;
        if (B <= 0) B = 1;
        int T = (int)(ne / B);
        sticky_sign_generic<<<(int)B, 256>>>(edc, flips, out, T);
    }
}

// round 12
// speedup vs baseline: 1.3352x; 1.3352x over previous
#include <cuda_runtime.h>
#include <cstdint>

#define NROWS   256
#define TM1     131072                     // outputs per row
#define TROW    131073                     // edc row length
#define CTAS_PER_ROW 128                   // 1024 outputs per CTA
#define GRID    (NROWS * CTAS_PER_ROW)     // 32768 CTAs
#define FULLM   0xffffffffu

// Decoupled-lookback status: one word per CTA.
//   0      = invalid
//   2 | p  = aggregate ready, parity p (bit 0)
//   4 | p  = inclusive prefix ready, parity p
// Payload and flag share one 32-bit word -> volatile ld/st suffice (no fence).
__device__ volatile unsigned int g_status[GRID];

__device__ __forceinline__ float sqrt_approx(float x) {
    float r;
    asm("sqrt.approx.f32 %0, %1;" : "=f"(r) : "f"(x));
    return r;
}

// ---------------------------------------------------------------------------
// K0: zero the status array (131 KB).
// ---------------------------------------------------------------------------
__global__ void __launch_bounds__(512)
init_status_kernel()
{
    g_status[blockIdx.x * 512 + threadIdx.x] = 0u;
}

// ---------------------------------------------------------------------------
// K1 (fused): single pass over flips+edc, per-row decoupled lookback with a
// WARP-PARALLEL 32-wide window (max 4 hops per CTA, vs 127 serial reads in
// the failed R9 version). edc/flips loads issued before the scan so DRAM
// latency overlaps the lookback.
// ---------------------------------------------------------------------------
__global__ void __launch_bounds__(256)
fused_kernel(const float* __restrict__ edc,
             const int*   __restrict__ flips,
             float*       __restrict__ out)
{
    const int blk  = blockIdx.x;
    const int tid  = threadIdx.x;
    const int lane = tid & 31;
    const int warp = tid >> 5;                       // 8 warps
    const uint32_t ltmask = (1u << lane) - 1u;

    const int row  = blk >> 7;
    const int c    = blk & (CTAS_PER_ROW - 1);
    const int gidx = blk * 256 + tid;                // 4-output group id

    // ---- issue all global loads up front (overlap with scan/lookback) ----
    const unsigned u0 = ((unsigned)gidx << 2) + (unsigned)row;  // edc flat
    const unsigned ub = u0 & ~3u;
    const float4* ep  = reinterpret_cast<const float4*>(edc) + (ub >> 2);
    const float4 A = __ldg(ep);
    const float4 B = __ldg(ep + 1);
    const int4   f = __ldg(reinterpret_cast<const int4*>(flips) + gidx);

    // ---- CTA parity scan --------------------------------------------------
    uint32_t p0 = (uint32_t)f.x & 1u;
    const uint32_t p1 = (uint32_t)f.y & 1u;
    const uint32_t p2 = (uint32_t)f.z & 1u;
    const uint32_t p3 = (uint32_t)f.w & 1u;
    if (c == 0 && tid == 0) p0 = 0u;                 // flips[:,0] never applied

    const uint32_t tp  = p0 ^ p1 ^ p2 ^ p3;
    const uint32_t bal = __ballot_sync(FULLM, tp != 0u);
    const uint32_t laneExcl = (uint32_t)__popc(bal & ltmask) & 1u;
    const uint32_t wtot     = (uint32_t)__popc(bal) & 1u;

    __shared__ uint32_t sW[8];
    __shared__ uint32_t sPrefix;
    if (lane == 0) sW[warp] = wtot;
    __syncthreads();

    uint32_t ctaTot = 0u, warpExcl = 0u;
#pragma unroll
    for (int w = 0; w < 8; ++w) {
        const uint32_t v = sW[w];
        ctaTot ^= v;
        if (w < warp) warpExcl ^= v;
    }

    // ---- decoupled lookback: warp 0, 32-wide windows ----------------------
    if (warp == 0) {
        if (c == 0) {
            if (lane == 0) {
                g_status[blk] = 4u | ctaTot;         // inclusive prefix ready
                sPrefix = 0u;
            }
        } else {
            if (lane == 0) g_status[blk] = 2u | ctaTot;   // publish aggregate

            uint32_t excl = 0u;
            int base      = blk;   // window end (exclusive)
            int remaining = c;     // predecessors left (all in this row)
            for (;;) {
                const int n   = remaining < 32 ? remaining : 32;
                const int idx = base - n + lane;
                uint32_t s = (lane < n) ? g_status[idx] : 4u;
                while (__any_sync(FULLM, s == 0u)) {
                    if (s == 0u) s = g_status[idx];
                }
                const uint32_t pmask = __ballot_sync(FULLM, (lane < n) && (s & 4u));
                if (pmask != 0u) {
                    const int h = 31 - __clz(pmask);        // closest prefix to us
                    const uint32_t cm =
                        __ballot_sync(FULLM, (lane < n) && (lane >= h) && (s & 1u));
                    excl ^= (uint32_t)__popc(cm) & 1u;
                    break;
                }
                const uint32_t cm = __ballot_sync(FULLM, (lane < n) && (s & 1u));
                excl ^= (uint32_t)__popc(cm) & 1u;
                base      -= n;
                remaining -= n;
                if (remaining == 0) break;          // hit row start: all combined
            }
            if (lane == 0) {
                g_status[blk] = 4u | ((excl ^ ctaTot) & 1u);
                sPrefix = excl;
            }
        }
    }
    __syncthreads();
    const uint32_t pref = sPrefix;

    // ---- amp body (identical math to R8) ---------------------------------
    const int delta = row & 3;                       // uniform per CTA
    float e0, e1, e2, e3, e4;
    switch (delta) {
    case 0:  e0 = A.x; e1 = A.y; e2 = A.z; e3 = A.w; e4 = B.x; break;
    case 1:  e0 = A.y; e1 = A.z; e2 = A.w; e3 = B.x; e4 = B.y; break;
    case 2:  e0 = A.z; e1 = A.w; e2 = B.x; e3 = B.y; e4 = B.z; break;
    default: e0 = A.w; e1 = B.x; e2 = B.y; e3 = B.z; e4 = B.w; break;
    }

    uint32_t run = pref ^ warpExcl ^ laneExcl;
    float4 o;
    run ^= p0;
    o.x = __uint_as_float(__float_as_uint(sqrt_approx(fmaxf(e0 - e1, 0.0f))) ^ (run << 31));
    run ^= p1;
    o.y = __uint_as_float(__float_as_uint(sqrt_approx(fmaxf(e1 - e2, 0.0f))) ^ (run << 31));
    run ^= p2;
    o.z = __uint_as_float(__float_as_uint(sqrt_approx(fmaxf(e2 - e3, 0.0f))) ^ (run << 31));
    run ^= p3;
    o.w = __uint_as_float(__float_as_uint(sqrt_approx(fmaxf(e3 - e4, 0.0f))) ^ (run << 31));

    reinterpret_cast<float4*>(out)[gidx] = o;
}

// ---------------------------------------------------------------------------
// Generic fallback: any (B, T). One CTA per row, chunked block-wide parity
// scan with a carried prefix. Only used if sizes don't match the constants.
// ---------------------------------------------------------------------------
__global__ void sticky_sign_generic(const float* __restrict__ edc,
                                    const int*   __restrict__ flips,
                                    float*       __restrict__ out,
                                    int T)
{
    const int row  = blockIdx.x;
    const int n    = T - 1;
    const int tid  = threadIdx.x;
    const int lane = tid & 31;
    const int warp = tid >> 5;

    const float* erow = edc   + (size_t)row * T;
    const int*   frow = flips + (size_t)row * n;
    float*       orow = out   + (size_t)row * n;

    __shared__ uint32_t sW[32];
    __shared__ uint32_t sCarry;
    if (tid == 0) sCarry = 0u;
    const int nwarps = (blockDim.x + 31) >> 5;
    if (tid < 32) sW[tid] = 0u;
    __syncthreads();

    for (int base = 0; base < n; base += blockDim.x) {
        const int i = base + tid;
        uint32_t f = 0u;
        if (i < n && i > 0) f = (uint32_t)frow[i] & 1u;

        const uint32_t m = __ballot_sync(0xffffffffu, f);
        const uint32_t laneIncl = (uint32_t)__popc(m & ((2u << lane) - 1u)) & 1u;
        if (lane == 0) sW[warp] = (uint32_t)__popc(m) & 1u;
        __syncthreads();

        uint32_t wpre = 0u, tot = 0u;
        for (int w = 0; w < nwarps; ++w) {
            uint32_t v = sW[w];
            tot ^= v;
            if (w < warp) wpre ^= v;
        }
        const uint32_t carry = sCarry;
        const uint32_t incl  = carry ^ wpre ^ laneIncl;

        if (i < n) {
            float amp = sqrtf(fmaxf(erow[i] - erow[i + 1], 0.0f));
            orow[i] = __uint_as_float(__float_as_uint(amp) ^ (incl << 31));
        }
        __syncthreads();
        if (tid == 0) sCarry = carry ^ tot;
        __syncthreads();
    }
}

extern "C" void kernel_launch(void* const* d_in, const int* in_sizes, int n_in,
                              void* d_out, int out_size)
{
    // Identify inputs by element count (edc has B extra elements).
    long long n0 = in_sizes[0];
    long long n1 = (n_in > 1) ? in_sizes[1] : 0;

    const float* edc;
    const int*   flips;
    long long ne, nf;
    if (n0 >= n1) {
        edc = (const float*)d_in[0];  flips = (const int*)d_in[1];
        ne = n0; nf = n1;
    } else {
        edc = (const float*)d_in[1];  flips = (const int*)d_in[0];
        ne = n1; nf = n0;
    }
    float* out = (float*)d_out;

    if (ne == (long long)NROWS * TROW && nf == (long long)NROWS * TM1) {
        init_status_kernel<<<GRID / 512, 512>>>();
        fused_kernel<<<GRID, 256>>>(edc, flips, out);
    } else {
        long long B = ne - nf;
        if (B <= 0) B = 1;
        int T = (int)(ne / B);
        sticky_sign_generic<<<(int)B, 256>>>(edc, flips, out, T);
    }
}

// round 13
// speedup vs baseline: 4.7066x; 3.5250x over previous
#include <cuda_runtime.h>
#include <cstdint>

#define NROWS   256
#define TM1     131072                     // outputs per row
#define TROW    131073                     // edc row length
#define CHUNKS_PER_ROW 128                 // 1024 outputs per chunk
#define NCHUNKS (NROWS * CHUNKS_PER_ROW)   // 32768
#define NGROUPS ((size_t)NROWS * TM1 / 4)  // 8,388,608 4-output groups
#define FULLM   0xffffffffu

// g_packed byte: bits[0:3] = 4 flip bits of the group,
//                bit 4     = exclusive flip-parity within its 1024-flip chunk
__device__ unsigned char g_packed[NGROUPS];        // 8.4 MB
// g_aggbits: bit (c) of word (row*4 + c/32) = aggregate parity of chunk c of row
__device__ unsigned int  g_aggbits[NROWS * 4];     // 4 KB, zeroed by init kernel

__device__ __forceinline__ float sqrt_approx(float x) {
    float r;
    asm("sqrt.approx.f32 %0, %1;" : "=f"(r) : "f"(x));
    return r;
}

// ---------------------------------------------------------------------------
// K0: zero the aggregate bitmask (1024 words).
// ---------------------------------------------------------------------------
__global__ void init_agg_kernel()
{
    g_aggbits[threadIdx.x] = 0u;
}

// ---------------------------------------------------------------------------
// K1 (pack): one 256-thr CTA per 1024-flip chunk; one int4 per thread.
// One ballot + one 8-word smem combine per thread (no serial chain).
// Emits packed byte (nibble + in-chunk excl parity) and the chunk aggregate
// as one atomicOr bit.
// ---------------------------------------------------------------------------
__global__ void __launch_bounds__(256)
pack_kernel(const int* __restrict__ flips)
{
    const int blk  = blockIdx.x;                 // chunk id
    const int tid  = threadIdx.x;
    const int lane = tid & 31;
    const int warp = tid >> 5;                   // 8 warps
    const uint32_t ltmask = (1u << lane) - 1u;

    const int row  = blk >> 7;
    const int c    = blk & (CHUNKS_PER_ROW - 1);
    const int gidx = blk * 256 + tid;            // 4-flip group id

    const int4 f = __ldg(reinterpret_cast<const int4*>(flips) + gidx);
    uint32_t p0 = (uint32_t)f.x & 1u;
    const uint32_t p1 = (uint32_t)f.y & 1u;
    const uint32_t p2 = (uint32_t)f.z & 1u;
    const uint32_t p3 = (uint32_t)f.w & 1u;
    if (c == 0 && tid == 0) p0 = 0u;             // flips[:,0] never applied

    const uint32_t nib = p0 | (p1 << 1) | (p2 << 2) | (p3 << 3);
    const uint32_t tp  = p0 ^ p1 ^ p2 ^ p3;
    const uint32_t bal = __ballot_sync(FULLM, tp != 0u);
    const uint32_t laneExcl = (uint32_t)__popc(bal & ltmask) & 1u;
    const uint32_t wtot     = (uint32_t)__popc(bal) & 1u;

    __shared__ uint32_t sW[8];
    if (lane == 0) sW[warp] = wtot;
    __syncthreads();

    uint32_t ctaTot = 0u, warpExcl = 0u;
#pragma unroll
    for (int w = 0; w < 8; ++w) {
        const uint32_t v = sW[w];
        ctaTot ^= v;
        if (w < warp) warpExcl ^= v;
    }

    g_packed[gidx] = (unsigned char)(nib | ((warpExcl ^ laneExcl) << 4));

    if (tid == 0 && ctaTot)
        atomicOr(&g_aggbits[(row << 2) + (c >> 5)], 1u << (c & 31));
}

// ---------------------------------------------------------------------------
// K2 (amp): 128-thr CTA per 1024 outputs; 8 outputs / thread.
// Prefix parity from 4 uniform L2-resident bitmask words (popc+mask).
// 3 aligned LDG.128 for the 9-float edc window; both packed bytes are
// self-contained (own bit4). No smem, no syncs, no ballots.
// ---------------------------------------------------------------------------
__global__ void __launch_bounds__(128)
amp_kernel(const float* __restrict__ edc, float* __restrict__ out)
{
    const int blk = blockIdx.x;                  // chunk id (1024 outputs)
    const int tid = threadIdx.x;

    const int row = blk >> 7;
    const int c   = blk & (CHUNKS_PER_ROW - 1);

    // parity of all chunk aggregates before chunk c of this row
    const int      c32 = c >> 5;
    const uint32_t cm  = (1u << (c & 31)) - 1u;
    uint32_t par = 0u;
#pragma unroll
    for (int j = 0; j < 4; ++j) {
        const uint32_t w = g_aggbits[(row << 2) + j];
        const uint32_t m = (j < c32) ? FULLM : ((j == c32) ? cm : 0u);
        par ^= (uint32_t)__popc(w & m);
    }
    const uint32_t pref = par & 1u;

    // two packed bytes for this thread's 2 groups (8 outputs)
    const int T = blk * 128 + tid;               // pair index
    const uchar2 bb = *reinterpret_cast<const uchar2*>(g_packed + 2 * T);
    const uint32_t b0 = bb.x, b1 = bb.y;

    // edc window: 9 floats starting at u0 = 8*T + row -> 3 aligned float4
    const unsigned u0    = ((unsigned)T << 3) + (unsigned)row;
    const unsigned ub    = u0 & ~3u;
    const int      delta = row & 3;              // uniform per CTA

    const float4* ep = reinterpret_cast<const float4*>(edc) + (ub >> 2);
    const float4 A = __ldg(ep);
    const float4 B = __ldg(ep + 1);
    const float4 C = __ldg(ep + 2);

    float e0, e1, e2, e3, e4, e5, e6, e7, e8;
    switch (delta) {
    case 0:  e0=A.x; e1=A.y; e2=A.z; e3=A.w; e4=B.x; e5=B.y; e6=B.z; e7=B.w; e8=C.x; break;
    case 1:  e0=A.y; e1=A.z; e2=A.w; e3=B.x; e4=B.y; e5=B.z; e6=B.w; e7=C.x; e8=C.y; break;
    case 2:  e0=A.z; e1=A.w; e2=B.x; e3=B.y; e4=B.z; e5=B.w; e6=C.x; e7=C.y; e8=C.z; break;
    default: e0=A.w; e1=B.x; e2=B.y; e3=B.z; e4=B.w; e5=C.x; e6=C.y; e7=C.z; e8=C.w; break;
    }

    float4 o0, o1;
    uint32_t run = pref ^ ((b0 >> 4) & 1u);
    run ^= b0 & 1u;
    o0.x = __uint_as_float(__float_as_uint(sqrt_approx(fmaxf(e0 - e1, 0.0f))) ^ (run << 31));
    run ^= (b0 >> 1) & 1u;
    o0.y = __uint_as_float(__float_as_uint(sqrt_approx(fmaxf(e1 - e2, 0.0f))) ^ (run << 31));
    run ^= (b0 >> 2) & 1u;
    o0.z = __uint_as_float(__float_as_uint(sqrt_approx(fmaxf(e2 - e3, 0.0f))) ^ (run << 31));
    run ^= (b0 >> 3) & 1u;
    o0.w = __uint_as_float(__float_as_uint(sqrt_approx(fmaxf(e3 - e4, 0.0f))) ^ (run << 31));

    run = pref ^ ((b1 >> 4) & 1u);
    run ^= b1 & 1u;
    o1.x = __uint_as_float(__float_as_uint(sqrt_approx(fmaxf(e4 - e5, 0.0f))) ^ (run << 31));
    run ^= (b1 >> 1) & 1u;
    o1.y = __uint_as_float(__float_as_uint(sqrt_approx(fmaxf(e5 - e6, 0.0f))) ^ (run << 31));
    run ^= (b1 >> 2) & 1u;
    o1.z = __uint_as_float(__float_as_uint(sqrt_approx(fmaxf(e6 - e7, 0.0f))) ^ (run << 31));
    run ^= (b1 >> 3) & 1u;
    o1.w = __uint_as_float(__float_as_uint(sqrt_approx(fmaxf(e7 - e8, 0.0f))) ^ (run << 31));

    float4* op = reinterpret_cast<float4*>(out) + 2 * T;
    op[0] = o0;
    op[1] = o1;
}

// ---------------------------------------------------------------------------
// Generic fallback: any (B, T). One CTA per row, chunked block-wide parity
// scan with a carried prefix. Only used if sizes don't match the constants.
// ---------------------------------------------------------------------------
__global__ void sticky_sign_generic(const float* __restrict__ edc,
                                    const int*   __restrict__ flips,
                                    float*       __restrict__ out,
                                    int T)
{
    const int row  = blockIdx.x;
    const int n    = T - 1;
    const int tid  = threadIdx.x;
    const int lane = tid & 31;
    const int warp = tid >> 5;

    const float* erow = edc   + (size_t)row * T;
    const int*   frow = flips + (size_t)row * n;
    float*       orow = out   + (size_t)row * n;

    __shared__ uint32_t sW[32];
    __shared__ uint32_t sCarry;
    if (tid == 0) sCarry = 0u;
    const int nwarps = (blockDim.x + 31) >> 5;
    if (tid < 32) sW[tid] = 0u;
    __syncthreads();

    for (int base = 0; base < n; base += blockDim.x) {
        const int i = base + tid;
        uint32_t f = 0u;
        if (i < n && i > 0) f = (uint32_t)frow[i] & 1u;

        const uint32_t m = __ballot_sync(0xffffffffu, f);
        const uint32_t laneIncl = (uint32_t)__popc(m & ((2u << lane) - 1u)) & 1u;
        if (lane == 0) sW[warp] = (uint32_t)__popc(m) & 1u;
        __syncthreads();

        uint32_t wpre = 0u, tot = 0u;
        for (int w = 0; w < nwarps; ++w) {
            uint32_t v = sW[w];
            tot ^= v;
            if (w < warp) wpre ^= v;
        }
        const uint32_t carry = sCarry;
        const uint32_t incl  = carry ^ wpre ^ laneIncl;

        if (i < n) {
            float amp = sqrtf(fmaxf(erow[i] - erow[i + 1], 0.0f));
            orow[i] = __uint_as_float(__float_as_uint(amp) ^ (incl << 31));
        }
        __syncthreads();
        if (tid == 0) sCarry = carry ^ tot;
        __syncthreads();
    }
}

extern "C" void kernel_launch(void* const* d_in, const int* in_sizes, int n_in,
                              void* d_out, int out_size)
{
    // Identify inputs by element count (edc has B extra elements).
    long long n0 = in_sizes[0];
    long long n1 = (n_in > 1) ? in_sizes[1] : 0;

    const float* edc;
    const int*   flips;
    long long ne, nf;
    if (n0 >= n1) {
        edc = (const float*)d_in[0];  flips = (const int*)d_in[1];
        ne = n0; nf = n1;
    } else {
        edc = (const float*)d_in[1];  flips = (const int*)d_in[0];
        ne = n1; nf = n0;
    }
    float* out = (float*)d_out;

    if (ne == (long long)NROWS * TROW && nf == (long long)NROWS * TM1) {
        init_agg_kernel<<<1, NROWS * 4>>>();
        pack_kernel<<<NCHUNKS, 256>>>(flips);
        amp_kernel<<<NCHUNKS, 128>>>(edc, out);
    } else {
        long long B = ne - nf;
        if (B <= 0) B = 1;
        int T = (int)(ne / B);
        sticky_sign_generic<<<(int)B, 256>>>(edc, flips, out, T);
    }
}